// round 4
// baseline (speedup 1.0000x reference)
#include <cuda_runtime.h>
#include <cstdint>

// Embedding gather: out[token, :] = weight[idx[token], :]
// idx: [8192] int32, weight: [32000, 512] f32, out: [8192, 512] f32
//
// Parallelism-maximized: 128-thread CTAs, 4 tokens per CTA, grid=2048.
// No smem / no barriers. Each thread front-batches 4 independent idx
// loads, then 4 independent LDG.128 gathers, then 4 STG.128.
// Warp lanes cover 32 consecutive float4 (512 B) of one row -> fully
// coalesced; idx load is a warp-broadcast.

static constexpr int VEC_PER_ROW    = 128;  // 512 f32 = 128 float4
static constexpr int TOKENS_PER_CTA = 4;
static constexpr int THREADS        = 128;

__global__ void __launch_bounds__(THREADS, 16)
embedding_gather_kernel(const int* __restrict__ idx,
                        const float4* __restrict__ weight,
                        float4* __restrict__ out)
{
    const int tid        = threadIdx.x;            // 0..127 = vec within row
    const int base_token = blockIdx.x * TOKENS_PER_CTA;

    // Independent index loads (warp-broadcast, cached).
    int rows[TOKENS_PER_CTA];
#pragma unroll
    for (int k = 0; k < TOKENS_PER_CTA; k++)
        rows[k] = __ldg(&idx[base_token + k]);

    // Front-batched independent gathers: MLP = 4 per thread.
    float4 v[TOKENS_PER_CTA];
#pragma unroll
    for (int k = 0; k < TOKENS_PER_CTA; k++)
        v[k] = __ldg(&weight[(long long)rows[k] * VEC_PER_ROW + tid]);

#pragma unroll
    for (int k = 0; k < TOKENS_PER_CTA; k++)
        out[(long long)(base_token + k) * VEC_PER_ROW + tid] = v[k];
}

extern "C" void kernel_launch(void* const* d_in, const int* in_sizes, int n_in,
                              void* d_out, int out_size)
{
    const int*   idx    = (const int*)d_in[0];    // x: [4, 2048] int32
    const float* weight = (const float*)d_in[1];  // [32000, 512] f32
    float*       out    = (float*)d_out;          // [4, 2048, 512] f32

    const int n_tokens = in_sizes[0];             // 8192
    const int n_ctas   = n_tokens / TOKENS_PER_CTA; // 2048

    embedding_gather_kernel<<<n_ctas, THREADS>>>(
        idx, (const float4*)weight, (float4*)out);
}